// round 3
// baseline (speedup 1.0000x reference)
#include <cuda_runtime.h>
#include <math.h>

#define B_ 512
#define C_ 64
#define H_ 128
#define P_ 16
#define G_ 2
#define EPS_ 1e-5f

// ---------------- device scratch (static, allocation-free) ----------------
__device__ float  g_ec[C_ * H_];      // layernormed emb_column
__device__ float  g_hp[P_ * H_];      // ep @ W1^T + lin_b + ep
__device__ float  g_W2t[H_ * H_];     // W2^T
__device__ float4 g_pc[P_];           // per-prompt: {|w|, max(-w,0), gn_w, gn_b}
__device__ float  g_gc[2 * 4];        // per-group: {A1, A2, B1, B2}

// ---------------- K1: parallel setup (6 blocks, 512 threads) ----------------
__global__ __launch_bounds__(512)
void setup_kernel(const float* __restrict__ emb_column,
                  const float* __restrict__ emb_prompt,
                  const float* __restrict__ lin_w,
                  const float* __restrict__ lin_b,
                  const float* __restrict__ ln_col_w,
                  const float* __restrict__ ln_col_b,
                  const float* __restrict__ ln_pr_w,
                  const float* __restrict__ ln_pr_b,
                  const float* __restrict__ expand_weight,
                  const float* __restrict__ gn_w,
                  const float* __restrict__ gn_b)
{
    __shared__ float s_ep[P_][H_];       // block 0
    __shared__ float s_t[H_ * 33];       // block 0: W1 k-tile
    __shared__ float s_tt[32 * 129];     // blocks 2..5

    const int tid  = threadIdx.x;
    const int warp = tid >> 5;
    const int lane = tid & 31;
    const int bid  = blockIdx.x;

    if (bid == 1) {
        // layernorm emb_column -> g_ec (64 rows / 16 warps)
        for (int r = warp; r < C_; r += 16) {
            const float* src = emb_column + r * H_;
            float v[4]; float s = 0.f, ss = 0.f;
            #pragma unroll
            for (int i = 0; i < 4; i++) { v[i] = src[lane + 32 * i]; s += v[i]; ss += v[i] * v[i]; }
            #pragma unroll
            for (int o = 16; o > 0; o >>= 1) {
                s  += __shfl_xor_sync(0xffffffffu, s,  o);
                ss += __shfl_xor_sync(0xffffffffu, ss, o);
            }
            const float mu  = s * (1.f / H_);
            const float inv = rsqrtf(ss * (1.f / H_) - mu * mu + EPS_);
            #pragma unroll
            for (int i = 0; i < 4; i++) {
                const int h = lane + 32 * i;
                g_ec[r * H_ + h] = (v[i] - mu) * inv * ln_col_w[h] + ln_col_b[h];
            }
        }
        return;
    }

    if (bid >= 2) {
        // coalesced W2 transpose, 32 h-rows per block
        const int h0 = (bid - 2) * 32;
        #pragma unroll
        for (int i = 0; i < 8; i++) {
            const int idx = tid + i * 512;           // 0..4095
            const int hh = idx >> 7, kk = idx & 127;
            s_tt[hh * 129 + kk] = lin_w[(h0 + hh) * (2 * H_) + H_ + kk];
        }
        __syncthreads();
        #pragma unroll
        for (int i = 0; i < 8; i++) {
            const int idx = tid + i * 512;
            const int k = idx >> 5, hl = idx & 31;
            g_W2t[k * H_ + h0 + hl] = s_tt[hl * 129 + k];
        }
        return;
    }

    // ---- block 0: ep layernorm (16 warps, 1 row each), hp GEMM, coefficients
    {
        const int r = warp;
        const float* src = emb_prompt + r * H_;
        float v[4]; float s = 0.f, ss = 0.f;
        #pragma unroll
        for (int i = 0; i < 4; i++) { v[i] = src[lane + 32 * i]; s += v[i]; ss += v[i] * v[i]; }
        #pragma unroll
        for (int o = 16; o > 0; o >>= 1) {
            s  += __shfl_xor_sync(0xffffffffu, s,  o);
            ss += __shfl_xor_sync(0xffffffffu, ss, o);
        }
        const float mu  = s * (1.f / H_);
        const float inv = rsqrtf(ss * (1.f / H_) - mu * mu + EPS_);
        #pragma unroll
        for (int i = 0; i < 4; i++) {
            const int h = lane + 32 * i;
            s_ep[r][h] = (v[i] - mu) * inv * ln_pr_w[h] + ln_pr_b[h];
        }
    }
    __syncthreads();

    // hp GEMM: thread = (h, pq), 4 p per thread
    {
        const int h  = tid & 127;
        const int pq = tid >> 7;   // 0..3, p = pq*4+j
        float acc[4];
        #pragma unroll
        for (int j = 0; j < 4; j++) {
            const int p = pq * 4 + j;
            acc[j] = lin_b[h] + s_ep[p][h];
        }
        for (int kt = 0; kt < H_; kt += 32) {
            #pragma unroll
            for (int i = 0; i < 8; i++) {
                const int idx = tid + i * 512;       // 128h x 32k
                const int hh = idx >> 5, jj = idx & 31;
                s_t[hh * 33 + jj] = lin_w[hh * (2 * H_) + kt + jj];
            }
            __syncthreads();
            #pragma unroll
            for (int j2 = 0; j2 < 32; j2++) {
                const float wk = s_t[h * 33 + j2];
                #pragma unroll
                for (int j = 0; j < 4; j++)
                    acc[j] += s_ep[pq * 4 + j][kt + j2] * wk;
            }
            __syncthreads();
        }
        #pragma unroll
        for (int j = 0; j < 4; j++)
            g_hp[(pq * 4 + j) * H_ + h] = acc[j];
    }

    if (tid == 0) {
        #pragma unroll
        for (int p = 0; p < P_; p++) {
            const float w = expand_weight[p];
            g_pc[p] = make_float4(fabsf(w), fmaxf(-w, 0.f), gn_w[p], gn_b[p]);
        }
        for (int g = 0; g < 2; g++) {
            float A1 = 0.f, A2 = 0.f, B1 = 0.f, B2 = 0.f;
            for (int p = g * 8; p < g * 8 + 8; p++) {
                const float w  = expand_weight[p];
                const float aw = fabsf(w);
                const float v  = fmaxf(-w, 0.f);
                const float u  = aw - v;
                A1 += aw; A2 += v; B1 += u * u; B2 += v * v;
            }
            g_gc[g * 4 + 0] = A1; g_gc[g * 4 + 1] = A2;
            g_gc[g * 4 + 2] = B1; g_gc[g * 4 + 3] = B2;
        }
    }
}

// ---------------- K2: fused per-batch kernel (512 blocks, 512 threads) ----------------
// smem layout (floats):
#define SM_EC    0                      // 64 x 132
#define SM_X     (64 * 132)             // 64 x 128
#define SM_XP    (SM_X + 64 * 128)      // 16 x 128  (reused as hat)
#define SM_PART  (SM_XP + 16 * 128)     // 4096 (phase1: [2][16][128]; phase2: [4][16][64])
#define SM_MCP   (SM_PART + 4096)       // 64 x 20  (m transposed [c][p], pad 20)
#define SM_RED   (SM_MCP + 64 * 20)     // 64
#define SM_GRP   (SM_RED + 64)          // 8
#define SM_FLOATS (SM_GRP + 8)          // 24136 floats = 96544 B

extern __shared__ float sm[];

__global__ void __launch_bounds__(512, 2)
trompt_main_kernel(const float* __restrict__ x,
                   const float* __restrict__ x_prompt,
                   float* __restrict__ out)
{
    float* s_ec   = sm + SM_EC;
    float* s_x    = sm + SM_X;
    float* s_xp   = sm + SM_XP;     // becomes hat after phase-1 reduce
    float* s_part = sm + SM_PART;
    float* s_mcp  = sm + SM_MCP;
    float* s_red  = sm + SM_RED;
    float* s_grp  = sm + SM_GRP;

    const int tid  = threadIdx.x;
    const int b    = blockIdx.x;
    const int warp = tid >> 5;
    const int lane = tid & 31;

    // ---- loads + fused batch stats
    {
        float s1 = 0.f, sx = 0.f, sr2 = 0.f, sx2 = 0.f;
        const float4* xb4 = (const float4*)(x + (size_t)b * (C_ * H_));
        #pragma unroll
        for (int i = 0; i < 4; i++) {
            const float4 v = xb4[tid + i * 512];
            *(float4*)(s_x + (tid + i * 512) * 4) = v;
            float vv[4] = {v.x, v.y, v.z, v.w};
            #pragma unroll
            for (int q = 0; q < 4; q++) {
                const float r = fmaxf(vv[q], 0.f);
                s1 += r; sx += vv[q]; sr2 += r * r; sx2 += vv[q] * vv[q];
            }
        }
        const float4* ec4 = (const float4*)g_ec;
        #pragma unroll
        for (int i = 0; i < 4; i++) {
            const int e = tid + i * 512;
            const float4 v = ec4[e];
            const int idx = e * 4;
            *(float4*)(s_ec + (idx >> 7) * 132 + (idx & 127)) = v;
        }
        const float4* xp4 = (const float4*)(x_prompt + (size_t)b * (P_ * H_));
        *(float4*)(s_xp + tid * 4) = xp4[tid];

        #pragma unroll
        for (int o = 16; o > 0; o >>= 1) {
            s1  += __shfl_xor_sync(0xffffffffu, s1,  o);
            sx  += __shfl_xor_sync(0xffffffffu, sx,  o);
            sr2 += __shfl_xor_sync(0xffffffffu, sr2, o);
            sx2 += __shfl_xor_sync(0xffffffffu, sx2, o);
        }
        if (lane == 0) {
            s_red[warp * 4 + 0] = s1;  s_red[warp * 4 + 1] = sx;
            s_red[warp * 4 + 2] = sr2; s_red[warp * 4 + 3] = sx2;
        }
    }
    __syncthreads();

    // ---- phase 1: hat = hp + xp + xp @ W2t ; thread = (h, pb2 of 8p, ks of 64k)
    {
        const int h   = tid & 127;
        const int pb2 = (tid >> 7) & 1;   // p base = pb2*8
        const int ks  = tid >> 8;         // k range [ks*64, ks*64+64)
        const int p0  = pb2 * 8;
        float acc[8];
        if (ks == 0) {
            #pragma unroll
            for (int j = 0; j < 8; j++)
                acc[j] = g_hp[(p0 + j) * H_ + h] + s_xp[(p0 + j) * H_ + h];
        } else {
            #pragma unroll
            for (int j = 0; j < 8; j++) acc[j] = 0.f;
        }
        const int k0 = ks * 64;
        for (int kq = 0; kq < 64; kq += 4) {
            const int k = k0 + kq;
            const float w0 = g_W2t[(k + 0) * H_ + h];
            const float w1 = g_W2t[(k + 1) * H_ + h];
            const float w2 = g_W2t[(k + 2) * H_ + h];
            const float w3 = g_W2t[(k + 3) * H_ + h];
            #pragma unroll
            for (int j = 0; j < 8; j++) {
                const float4 xp = *(const float4*)(s_xp + (p0 + j) * H_ + k);
                acc[j] += xp.x * w0 + xp.y * w1 + xp.z * w2 + xp.w * w3;
            }
        }
        #pragma unroll
        for (int j = 0; j < 8; j++)
            s_part[ks * 2048 + (p0 + j) * H_ + h] = acc[j];
    }
    __syncthreads();

    // ---- phase 1 reduce: hat (into s_xp region) = part[0] + part[1]
    {
        const float4 a = *(const float4*)(s_part + tid * 4);
        const float4 c = *(const float4*)(s_part + 2048 + tid * 4);
        float4 r; r.x = a.x + c.x; r.y = a.y + c.y; r.z = a.z + c.z; r.w = a.w + c.w;
        *(float4*)(s_xp + tid * 4) = r;
    }
    __syncthreads();

    // ---- phase 2: m[p,c] = sum_h hat[p,h]*ec[c,h] ; thread = (c, hs of 32h, pg of 8p)
    {
        const int c  = tid & 63;
        const int hs = (tid >> 6) & 3;
        const int pg = tid >> 8;
        const int p0 = pg * 8;
        float m[8] = {0.f,0.f,0.f,0.f,0.f,0.f,0.f,0.f};
        const int hb = hs * 32;
        #pragma unroll
        for (int hq = 0; hq < 32; hq += 4) {
            const int hh = hb + hq;
            const float4 e = *(const float4*)(s_ec + c * 132 + hh);
            #pragma unroll
            for (int j = 0; j < 8; j++) {
                const float4 t = *(const float4*)(s_xp + (p0 + j) * H_ + hh);
                m[j] += e.x * t.x + e.y * t.y + e.z * t.z + e.w * t.w;
            }
        }
        #pragma unroll
        for (int j = 0; j < 8; j++)
            s_part[hs * 1024 + (p0 + j) * 64 + c] = m[j];
    }
    __syncthreads();

    // ---- phase 2 reduce + softmax (warp = p) + group-stat fold (tid 0)
    {
        const int p  = warp;
        float v0 = 0.f, v1 = 0.f;
        #pragma unroll
        for (int hs = 0; hs < 4; hs++) {
            v0 += s_part[hs * 1024 + p * 64 + lane];
            v1 += s_part[hs * 1024 + p * 64 + 32 + lane];
        }
        float mx = fmaxf(v0, v1);
        #pragma unroll
        for (int o = 16; o > 0; o >>= 1)
            mx = fmaxf(mx, __shfl_xor_sync(0xffffffffu, mx, o));
        const float e0 = __expf(v0 - mx);
        const float e1 = __expf(v1 - mx);
        float s = e0 + e1;
        #pragma unroll
        for (int o = 16; o > 0; o >>= 1)
            s += __shfl_xor_sync(0xffffffffu, s, o);
        const float inv = 1.f / s;
        s_mcp[lane * 20 + p]        = e0 * inv;
        s_mcp[(lane + 32) * 20 + p] = e1 * inv;

        if (tid == 0) {
            float S1 = 0.f, Sx = 0.f, Sr2 = 0.f, Sx2 = 0.f;
            #pragma unroll
            for (int w = 0; w < 16; w++) {
                S1 += s_red[w * 4 + 0]; Sx  += s_red[w * 4 + 1];
                Sr2 += s_red[w * 4 + 2]; Sx2 += s_red[w * 4 + 3];
            }
            const float invN = 1.f / 65536.f;
            #pragma unroll
            for (int g = 0; g < 2; g++) {
                const float A1 = g_gc[g * 4 + 0], A2 = g_gc[g * 4 + 1];
                const float B1 = g_gc[g * 4 + 2], B2 = g_gc[g * 4 + 3];
                const float mu = (A1 * S1 - A2 * Sx) * invN;
                const float E2 = (B1 * Sr2 + B2 * (Sx2 - Sr2)) * invN;
                s_grp[g * 2 + 0] = mu;
                s_grp[g * 2 + 1] = rsqrtf(E2 - mu * mu + EPS_);
            }
        }
    }
    __syncthreads();

    // ---- phase 4: out[p,h] = c1*sum_c m*relu(x) + c2*sum_c m*x + c3 ; p = pb*4+j
    {
        const int h  = tid & 127;
        const int pb = tid >> 7;
        float c1[4], c2[4], c3[4], Rm[4] = {0,0,0,0}, Xm[4] = {0,0,0,0};
        #pragma unroll
        for (int j = 0; j < 4; j++) {
            const int p = pb * 4 + j;
            const float4 pc = g_pc[p];
            const int g = p >> 3;
            const float mu = s_grp[g * 2 + 0];
            const float rs = s_grp[g * 2 + 1];
            const float gr = pc.z * rs;
            c1[j] = gr * pc.x;
            c2[j] = 1.f - gr * pc.y;
            c3[j] = pc.w - gr * mu;
        }
        for (int c = 0; c < C_; c += 4) {
            float xv[4], rv[4];
            #pragma unroll
            for (int i = 0; i < 4; i++) {
                xv[i] = s_x[(c + i) * H_ + h];
                rv[i] = fmaxf(xv[i], 0.f);
            }
            #pragma unroll
            for (int i = 0; i < 4; i++) {
                const float4 m4 = *(const float4*)(s_mcp + (c + i) * 20 + pb * 4);
                Rm[0] += m4.x * rv[i]; Xm[0] += m4.x * xv[i];
                Rm[1] += m4.y * rv[i]; Xm[1] += m4.y * xv[i];
                Rm[2] += m4.z * rv[i]; Xm[2] += m4.z * xv[i];
                Rm[3] += m4.w * rv[i]; Xm[3] += m4.w * xv[i];
            }
        }
        float* ob = out + (size_t)b * (P_ * H_);
        #pragma unroll
        for (int j = 0; j < 4; j++)
            ob[(pb * 4 + j) * H_ + h] = c1[j] * Rm[j] + c2[j] * Xm[j] + c3[j];
    }
}

// ---------------- launch ----------------
extern "C" void kernel_launch(void* const* d_in, const int* in_sizes, int n_in,
                              void* d_out, int out_size)
{
    const float* x          = (const float*)d_in[0];
    const float* x_prompt   = (const float*)d_in[1];
    const float* emb_column = (const float*)d_in[2];
    const float* emb_prompt = (const float*)d_in[3];
    const float* lin_w      = (const float*)d_in[4];
    const float* lin_b      = (const float*)d_in[5];
    const float* ln_col_w   = (const float*)d_in[6];
    const float* ln_col_b   = (const float*)d_in[7];
    const float* ln_pr_w    = (const float*)d_in[8];
    const float* ln_pr_b    = (const float*)d_in[9];
    const float* expand_w   = (const float*)d_in[10];
    const float* gn_w       = (const float*)d_in[11];
    const float* gn_b       = (const float*)d_in[12];
    float* out = (float*)d_out;

    const int smemBytes = SM_FLOATS * (int)sizeof(float);   // 96,544 B
    cudaFuncSetAttribute(trompt_main_kernel,
                         cudaFuncAttributeMaxDynamicSharedMemorySize, smemBytes);

    setup_kernel<<<6, 512>>>(emb_column, emb_prompt, lin_w, lin_b,
                             ln_col_w, ln_col_b, ln_pr_w, ln_pr_b,
                             expand_w, gn_w, gn_b);
    trompt_main_kernel<<<B_, 512, smemBytes>>>(x, x_prompt, out);
}

// round 5
// speedup vs baseline: 1.2683x; 1.2683x over previous
#include <cuda_runtime.h>
#include <math.h>

#define B_ 512
#define C_ 64
#define H_ 128
#define P_ 16
#define G_ 2
#define EPS_ 1e-5f

typedef unsigned long long u64;

__device__ __forceinline__ u64 fma2(u64 a, u64 b, u64 c) {
    u64 d;
    asm("fma.rn.f32x2 %0, %1, %2, %3;" : "=l"(d) : "l"(a), "l"(b), "l"(c));
    return d;
}
__device__ __forceinline__ u64 pack2(float lo, float hi) {
    u64 d; asm("mov.b64 %0, {%1, %2};" : "=l"(d) : "f"(lo), "f"(hi)); return d;
}
__device__ __forceinline__ float2 unpack2(u64 v) {
    float2 r; asm("mov.b64 {%0, %1}, %2;" : "=f"(r.x), "=f"(r.y) : "l"(v)); return r;
}

// ---------------- device scratch ----------------
__device__ float  g_ec[C_ * H_];          // layernormed emb_column
__device__ float  g_hp[P_ * H_];          // ep @ W1^T + lin_b + ep
__device__ float4 g_W2q[32 * H_];         // W2 packed: g_W2q[kq*H + h] = (W2t[4kq..4kq+3][h])
__device__ float4 g_pc[P_];               // {|w|, max(-w,0), gn_w, gn_b}
__device__ float  g_gc[2 * 4];            // per-group {A1,A2,B1,B2}

// ---------------- K1: parallel setup (9 blocks, 512 threads) ----------------
__global__ __launch_bounds__(512)
void setup_kernel(const float* __restrict__ emb_column,
                  const float* __restrict__ emb_prompt,
                  const float* __restrict__ lin_w,
                  const float* __restrict__ lin_b,
                  const float* __restrict__ ln_col_w,
                  const float* __restrict__ ln_col_b,
                  const float* __restrict__ ln_pr_w,
                  const float* __restrict__ ln_pr_b,
                  const float* __restrict__ expand_weight,
                  const float* __restrict__ gn_w,
                  const float* __restrict__ gn_b)
{
    __shared__ float s_ep[4][H_];        // hp blocks
    __shared__ float s_t[H_ * 33];       // hp blocks: W1 k-tile
    __shared__ float s_tt[32 * 132];     // repack blocks

    const int tid  = threadIdx.x;
    const int warp = tid >> 5;
    const int lane = tid & 31;
    const int bid  = blockIdx.x;

    if (bid == 4) {
        // layernorm emb_column -> g_ec
        for (int r = warp; r < C_; r += 16) {
            const float* src = emb_column + r * H_;
            float v[4]; float s = 0.f, ss = 0.f;
            #pragma unroll
            for (int i = 0; i < 4; i++) { v[i] = src[lane + 32 * i]; s += v[i]; ss += v[i] * v[i]; }
            #pragma unroll
            for (int o = 16; o > 0; o >>= 1) {
                s  += __shfl_xor_sync(0xffffffffu, s,  o);
                ss += __shfl_xor_sync(0xffffffffu, ss, o);
            }
            const float mu  = s * (1.f / H_);
            const float inv = rsqrtf(ss * (1.f / H_) - mu * mu + EPS_);
            #pragma unroll
            for (int i = 0; i < 4; i++) {
                const int h = lane + 32 * i;
                g_ec[r * H_ + h] = (v[i] - mu) * inv * ln_col_w[h] + ln_col_b[h];
            }
        }
        return;
    }

    if (bid >= 5) {
        // W2 repack: h-chunk of 32 rows -> g_W2q[kq][h] = W2[h][4kq..4kq+3]
        const int h0 = (bid - 5) * 32;
        #pragma unroll
        for (int i = 0; i < 8; i++) {
            const int idx = tid + i * 512;           // 32h x 128k
            const int hh = idx >> 7, kk = idx & 127;
            s_tt[hh * 132 + kk] = lin_w[(h0 + hh) * (2 * H_) + H_ + kk];
        }
        __syncthreads();
        #pragma unroll
        for (int i = 0; i < 2; i++) {
            const int idx = tid + i * 512;           // 32kq x 32hl
            const int kq = idx >> 5, hl = idx & 31;
            g_W2q[kq * H_ + h0 + hl] = *(const float4*)(s_tt + hl * 132 + 4 * kq);
        }
        return;
    }

    // ---- hp blocks (bid 0..3): p group p0..p0+3
    const int p0 = bid * 4;
    if (warp < 4) {
        const int r = warp;
        const float* src = emb_prompt + (p0 + r) * H_;
        float v[4]; float s = 0.f, ss = 0.f;
        #pragma unroll
        for (int i = 0; i < 4; i++) { v[i] = src[lane + 32 * i]; s += v[i]; ss += v[i] * v[i]; }
        #pragma unroll
        for (int o = 16; o > 0; o >>= 1) {
            s  += __shfl_xor_sync(0xffffffffu, s,  o);
            ss += __shfl_xor_sync(0xffffffffu, ss, o);
        }
        const float mu  = s * (1.f / H_);
        const float inv = rsqrtf(ss * (1.f / H_) - mu * mu + EPS_);
        #pragma unroll
        for (int i = 0; i < 4; i++) {
            const int h = lane + 32 * i;
            s_ep[r][h] = (v[i] - mu) * inv * ln_pr_w[h] + ln_pr_b[h];
        }
    }
    __syncthreads();

    {
        const int h = tid & 127;
        const int j = tid >> 7;   // 0..3
        float acc = lin_b[h] + s_ep[j][h];
        for (int kt = 0; kt < H_; kt += 32) {
            #pragma unroll
            for (int i = 0; i < 8; i++) {
                const int idx = tid + i * 512;       // 128h x 32k
                const int hh = idx >> 5, kk = idx & 31;
                s_t[hh * 33 + kk] = lin_w[hh * (2 * H_) + kt + kk];
            }
            __syncthreads();
            #pragma unroll
            for (int j2 = 0; j2 < 32; j2++)
                acc += s_t[h * 33 + j2] * s_ep[j][kt + j2];
            __syncthreads();
        }
        g_hp[(p0 + j) * H_ + h] = acc;
    }

    if (bid == 0 && tid == 0) {
        #pragma unroll
        for (int p = 0; p < P_; p++) {
            const float w = expand_weight[p];
            g_pc[p] = make_float4(fabsf(w), fmaxf(-w, 0.f), gn_w[p], gn_b[p]);
        }
        for (int g = 0; g < 2; g++) {
            float A1 = 0.f, A2 = 0.f, B1 = 0.f, B2 = 0.f;
            for (int p = g * 8; p < g * 8 + 8; p++) {
                const float w  = expand_weight[p];
                const float aw = fabsf(w);
                const float v  = fmaxf(-w, 0.f);
                const float u  = aw - v;
                A1 += aw; A2 += v; B1 += u * u; B2 += v * v;
            }
            g_gc[g * 4 + 0] = A1; g_gc[g * 4 + 1] = A2;
            g_gc[g * 4 + 2] = B1; g_gc[g * 4 + 3] = B2;
        }
    }
}

// ---------------- K2: fused per-batch kernel (512 blocks, 512 threads) ----------------
// NOTE: s_md rows hold 16 prompts x 2 duplicated floats = 32 floats; padded to 36
// (144B row: 16B-aligned for any c, 4-way-conflict softmax stores instead of 32-way).
#define SM_EC    0                       // 64 x 132
#define SM_X     (64 * 132)              // 64 x 128
#define SM_XP    (SM_X + 64 * 128)       // 16 x 128
#define SM_HAT   (SM_XP + 16 * 128)      // 16 x 128
#define SM_M     (SM_HAT + 16 * 128)     // 16 x 64
#define SM_MD    (SM_M + 16 * 64)        // 64 x 36 (duplicated transposed m, stride 36)
#define SM_RED   (SM_MD + 64 * 36)       // 64
#define SM_GRP   (SM_RED + 64)           // 8
#define SM_FLOATS (SM_GRP + 8)           // 24136 floats = 96,544 B

extern __shared__ float sm[];

__global__ void __launch_bounds__(512, 2)
trompt_main_kernel(const float* __restrict__ x,
                   const float* __restrict__ x_prompt,
                   float* __restrict__ out)
{
    float* s_ec  = sm + SM_EC;
    float* s_x   = sm + SM_X;
    float* s_xp  = sm + SM_XP;
    float* s_hat = sm + SM_HAT;
    float* s_m   = sm + SM_M;
    float* s_md  = sm + SM_MD;
    float* s_red = sm + SM_RED;
    float* s_grp = sm + SM_GRP;

    const int tid  = threadIdx.x;
    const int b    = blockIdx.x;
    const int warp = tid >> 5;
    const int lane = tid & 31;

    // ---- loads + fused batch stats
    {
        float s1 = 0.f, sx = 0.f, sr2 = 0.f, sx2 = 0.f;
        const float4* xb4 = (const float4*)(x + (size_t)b * (C_ * H_));
        #pragma unroll
        for (int i = 0; i < 4; i++) {
            const float4 v = xb4[tid + i * 512];
            *(float4*)(s_x + (tid + i * 512) * 4) = v;
            float vv[4] = {v.x, v.y, v.z, v.w};
            #pragma unroll
            for (int q = 0; q < 4; q++) {
                const float r = fmaxf(vv[q], 0.f);
                s1 += r; sx += vv[q]; sr2 += r * r; sx2 += vv[q] * vv[q];
            }
        }
        const float4* ec4 = (const float4*)g_ec;
        #pragma unroll
        for (int i = 0; i < 4; i++) {
            const int e = tid + i * 512;
            const float4 v = ec4[e];
            const int idx = e * 4;
            *(float4*)(s_ec + (idx >> 7) * 132 + (idx & 127)) = v;
        }
        const float4* xp4 = (const float4*)(x_prompt + (size_t)b * (P_ * H_));
        *(float4*)(s_xp + tid * 4) = xp4[tid];

        #pragma unroll
        for (int o = 16; o > 0; o >>= 1) {
            s1  += __shfl_xor_sync(0xffffffffu, s1,  o);
            sx  += __shfl_xor_sync(0xffffffffu, sx,  o);
            sr2 += __shfl_xor_sync(0xffffffffu, sr2, o);
            sx2 += __shfl_xor_sync(0xffffffffu, sx2, o);
        }
        if (lane == 0) {
            s_red[warp * 4 + 0] = s1;  s_red[warp * 4 + 1] = sx;
            s_red[warp * 4 + 2] = sr2; s_red[warp * 4 + 3] = sx2;
        }
    }
    __syncthreads();

    const int h  = tid & 127;
    const int pb = tid >> 7;    // 0..3

    // ---- phase 1: hat[p,h] = hp + xp + xp @ W2   (packed f32x2, p = pb*4+j)
    {
        u64 aa[4] = {0,0,0,0}, ab[4] = {0,0,0,0};
        const ulonglong2* w2 = (const ulonglong2*)g_W2q;
        for (int kq = 0; kq < 32; kq++) {
            const ulonglong2 w = w2[kq * H_ + h];
            #pragma unroll
            for (int j = 0; j < 4; j++) {
                const ulonglong2 xp = *(const ulonglong2*)(s_xp + (pb * 4 + j) * H_ + kq * 4);
                aa[j] = fma2(xp.x, w.x, aa[j]);
                ab[j] = fma2(xp.y, w.y, ab[j]);
            }
        }
        #pragma unroll
        for (int j = 0; j < 4; j++) {
            const int p = pb * 4 + j;
            const float2 ra = unpack2(aa[j]);
            const float2 rb = unpack2(ab[j]);
            s_hat[p * H_ + h] = (ra.x + ra.y) + (rb.x + rb.y)
                              + g_hp[p * H_ + h] + s_xp[p * H_ + h];
        }
    }
    __syncthreads();

    // ---- phase 2: m[p,c] = sum_h hat[p,h]*ec[c,h]  (packed)
    {
        const int c  = tid & 63;
        const int pq = tid >> 6;   // 0..7
        u64 a0a = 0, a0b = 0, a1a = 0, a1b = 0;
        for (int hh = 0; hh < H_; hh += 4) {
            const ulonglong2 e  = *(const ulonglong2*)(s_ec + c * 132 + hh);
            const ulonglong2 t0 = *(const ulonglong2*)(s_hat + pq * H_ + hh);
            const ulonglong2 t1 = *(const ulonglong2*)(s_hat + (pq + 8) * H_ + hh);
            a0a = fma2(e.x, t0.x, a0a);
            a0b = fma2(e.y, t0.y, a0b);
            a1a = fma2(e.x, t1.x, a1a);
            a1b = fma2(e.y, t1.y, a1b);
        }
        const float2 r0a = unpack2(a0a), r0b = unpack2(a0b);
        const float2 r1a = unpack2(a1a), r1b = unpack2(a1b);
        s_m[pq * 64 + c]       = (r0a.x + r0a.y) + (r0b.x + r0b.y);
        s_m[(pq + 8) * 64 + c] = (r1a.x + r1a.y) + (r1b.x + r1b.y);
    }
    __syncthreads();

    // ---- softmax (warp = p) writing duplicated transposed m; tid0 folds group stats
    {
        const int p = warp;
        const float v0 = s_m[p * 64 + lane];
        const float v1 = s_m[p * 64 + 32 + lane];
        float mx = fmaxf(v0, v1);
        #pragma unroll
        for (int o = 16; o > 0; o >>= 1)
            mx = fmaxf(mx, __shfl_xor_sync(0xffffffffu, mx, o));
        const float e0 = __expf(v0 - mx);
        const float e1 = __expf(v1 - mx);
        float s = e0 + e1;
        #pragma unroll
        for (int o = 16; o > 0; o >>= 1)
            s += __shfl_xor_sync(0xffffffffu, s, o);
        const float inv = 1.f / s;
        const float r0 = e0 * inv, r1 = e1 * inv;
        *(u64*)(s_md + lane * 36 + 2 * p)        = pack2(r0, r0);
        *(u64*)(s_md + (lane + 32) * 36 + 2 * p) = pack2(r1, r1);

        if (tid == 0) {
            float S1 = 0.f, Sx = 0.f, Sr2 = 0.f, Sx2 = 0.f;
            #pragma unroll
            for (int w = 0; w < 16; w++) {
                S1 += s_red[w * 4 + 0]; Sx  += s_red[w * 4 + 1];
                Sr2 += s_red[w * 4 + 2]; Sx2 += s_red[w * 4 + 3];
            }
            const float invN = 1.f / 65536.f;
            #pragma unroll
            for (int g = 0; g < 2; g++) {
                const float A1 = g_gc[g * 4 + 0], A2 = g_gc[g * 4 + 1];
                const float B1 = g_gc[g * 4 + 2], B2 = g_gc[g * 4 + 3];
                const float mu = (A1 * S1 - A2 * Sx) * invN;
                const float E2 = (B1 * Sr2 + B2 * (Sx2 - Sr2)) * invN;
                s_grp[g * 2 + 0] = mu;
                s_grp[g * 2 + 1] = rsqrtf(E2 - mu * mu + EPS_);
            }
        }
    }
    __syncthreads();

    // ---- phase 4: out[p,h], p = pb*4+j  (packed: acc = (Rm, Xm))
    {
        float c1[4], c2[4], c3[4];
        #pragma unroll
        for (int j = 0; j < 4; j++) {
            const int p = pb * 4 + j;
            const float4 pc = g_pc[p];
            const int g = p >> 3;
            const float mu = s_grp[g * 2 + 0];
            const float rs = s_grp[g * 2 + 1];
            const float gr = pc.z * rs;
            c1[j] = gr * pc.x;
            c2[j] = 1.f - gr * pc.y;
            c3[j] = pc.w - gr * mu;
        }
        u64 acc[4] = {0,0,0,0};
        for (int c = 0; c < C_; c++) {
            const float xv = s_x[c * H_ + h];
            const float rv = fmaxf(xv, 0.f);
            const u64 bvx = pack2(rv, xv);
            const ulonglong2 m01 = *(const ulonglong2*)(s_md + c * 36 + pb * 8);
            const ulonglong2 m23 = *(const ulonglong2*)(s_md + c * 36 + pb * 8 + 4);
            acc[0] = fma2(m01.x, bvx, acc[0]);
            acc[1] = fma2(m01.y, bvx, acc[1]);
            acc[2] = fma2(m23.x, bvx, acc[2]);
            acc[3] = fma2(m23.y, bvx, acc[3]);
        }
        float* ob = out + (size_t)b * (P_ * H_);
        #pragma unroll
        for (int j = 0; j < 4; j++) {
            const float2 rx = unpack2(acc[j]);   // (Rm, Xm)
            ob[(pb * 4 + j) * H_ + h] = c1[j] * rx.x + c2[j] * rx.y + c3[j];
        }
    }
}

// ---------------- launch ----------------
extern "C" void kernel_launch(void* const* d_in, const int* in_sizes, int n_in,
                              void* d_out, int out_size)
{
    const float* x          = (const float*)d_in[0];
    const float* x_prompt   = (const float*)d_in[1];
    const float* emb_column = (const float*)d_in[2];
    const float* emb_prompt = (const float*)d_in[3];
    const float* lin_w      = (const float*)d_in[4];
    const float* lin_b      = (const float*)d_in[5];
    const float* ln_col_w   = (const float*)d_in[6];
    const float* ln_col_b   = (const float*)d_in[7];
    const float* ln_pr_w    = (const float*)d_in[8];
    const float* ln_pr_b    = (const float*)d_in[9];
    const float* expand_w   = (const float*)d_in[10];
    const float* gn_w       = (const float*)d_in[11];
    const float* gn_b       = (const float*)d_in[12];
    float* out = (float*)d_out;

    const int smemBytes = SM_FLOATS * (int)sizeof(float);   // 96,544 B
    cudaFuncSetAttribute(trompt_main_kernel,
                         cudaFuncAttributeMaxDynamicSharedMemorySize, smemBytes);

    setup_kernel<<<9, 512>>>(emb_column, emb_prompt, lin_w, lin_b,
                             ln_col_w, ln_col_b, ln_pr_w, ln_pr_b,
                             expand_w, gn_w, gn_b);
    trompt_main_kernel<<<B_, 512, smemBytes>>>(x, x_prompt, out);
}

// round 6
// speedup vs baseline: 1.4609x; 1.1518x over previous
#include <cuda_runtime.h>
#include <math.h>

#define B_ 512
#define C_ 64
#define H_ 128
#define P_ 16
#define G_ 2
#define EPS_ 1e-5f

typedef unsigned long long u64;

__device__ __forceinline__ u64 fma2(u64 a, u64 b, u64 c) {
    u64 d;
    asm("fma.rn.f32x2 %0, %1, %2, %3;" : "=l"(d) : "l"(a), "l"(b), "l"(c));
    return d;
}
__device__ __forceinline__ u64 pack2(float lo, float hi) {
    u64 d; asm("mov.b64 %0, {%1, %2};" : "=l"(d) : "f"(lo), "f"(hi)); return d;
}
__device__ __forceinline__ float2 unpack2(u64 v) {
    float2 r; asm("mov.b64 {%0, %1}, %2;" : "=f"(r.x), "=f"(r.y) : "l"(v)); return r;
}

// ---------------- device scratch ----------------
__device__ float  g_ec[C_ * H_];          // layernormed emb_column
__device__ float  g_hp[P_ * H_];          // ep @ W1^T + lin_b + ep
__device__ float4 g_W2q[32 * H_];         // W2 packed: g_W2q[kq*H + h] = W2t[4kq..4kq+3][h]
__device__ float4 g_pc[P_];               // {|w|, max(-w,0), gn_w, gn_b}
__device__ float  g_gc[2 * 4];            // per-group {A1,A2,B1,B2}

// ---------------- K1: parallel setup (9 blocks, 512 threads) ----------------
__global__ __launch_bounds__(512)
void setup_kernel(const float* __restrict__ emb_column,
                  const float* __restrict__ emb_prompt,
                  const float* __restrict__ lin_w,
                  const float* __restrict__ lin_b,
                  const float* __restrict__ ln_col_w,
                  const float* __restrict__ ln_col_b,
                  const float* __restrict__ ln_pr_w,
                  const float* __restrict__ ln_pr_b,
                  const float* __restrict__ expand_weight,
                  const float* __restrict__ gn_w,
                  const float* __restrict__ gn_b)
{
    __shared__ float s_ep[4][H_];
    __shared__ float s_t[H_ * 33];
    __shared__ float s_tt[32 * 132];

    const int tid  = threadIdx.x;
    const int warp = tid >> 5;
    const int lane = tid & 31;
    const int bid  = blockIdx.x;

    if (bid == 4) {
        for (int r = warp; r < C_; r += 16) {
            const float* src = emb_column + r * H_;
            float v[4]; float s = 0.f, ss = 0.f;
            #pragma unroll
            for (int i = 0; i < 4; i++) { v[i] = src[lane + 32 * i]; s += v[i]; ss += v[i] * v[i]; }
            #pragma unroll
            for (int o = 16; o > 0; o >>= 1) {
                s  += __shfl_xor_sync(0xffffffffu, s,  o);
                ss += __shfl_xor_sync(0xffffffffu, ss, o);
            }
            const float mu  = s * (1.f / H_);
            const float inv = rsqrtf(ss * (1.f / H_) - mu * mu + EPS_);
            #pragma unroll
            for (int i = 0; i < 4; i++) {
                const int h = lane + 32 * i;
                g_ec[r * H_ + h] = (v[i] - mu) * inv * ln_col_w[h] + ln_col_b[h];
            }
        }
        return;
    }

    if (bid >= 5) {
        const int h0 = (bid - 5) * 32;
        #pragma unroll
        for (int i = 0; i < 8; i++) {
            const int idx = tid + i * 512;
            const int hh = idx >> 7, kk = idx & 127;
            s_tt[hh * 132 + kk] = lin_w[(h0 + hh) * (2 * H_) + H_ + kk];
        }
        __syncthreads();
        #pragma unroll
        for (int i = 0; i < 2; i++) {
            const int idx = tid + i * 512;
            const int kq = idx >> 5, hl = idx & 31;
            g_W2q[kq * H_ + h0 + hl] = *(const float4*)(s_tt + hl * 132 + 4 * kq);
        }
        return;
    }

    const int p0 = bid * 4;
    if (warp < 4) {
        const int r = warp;
        const float* src = emb_prompt + (p0 + r) * H_;
        float v[4]; float s = 0.f, ss = 0.f;
        #pragma unroll
        for (int i = 0; i < 4; i++) { v[i] = src[lane + 32 * i]; s += v[i]; ss += v[i] * v[i]; }
        #pragma unroll
        for (int o = 16; o > 0; o >>= 1) {
            s  += __shfl_xor_sync(0xffffffffu, s,  o);
            ss += __shfl_xor_sync(0xffffffffu, ss, o);
        }
        const float mu  = s * (1.f / H_);
        const float inv = rsqrtf(ss * (1.f / H_) - mu * mu + EPS_);
        #pragma unroll
        for (int i = 0; i < 4; i++) {
            const int h = lane + 32 * i;
            s_ep[r][h] = (v[i] - mu) * inv * ln_pr_w[h] + ln_pr_b[h];
        }
    }
    __syncthreads();

    {
        const int h = tid & 127;
        const int j = tid >> 7;
        float acc = lin_b[h] + s_ep[j][h];
        for (int kt = 0; kt < H_; kt += 32) {
            #pragma unroll
            for (int i = 0; i < 8; i++) {
                const int idx = tid + i * 512;
                const int hh = idx >> 5, kk = idx & 31;
                s_t[hh * 33 + kk] = lin_w[hh * (2 * H_) + kt + kk];
            }
            __syncthreads();
            #pragma unroll
            for (int j2 = 0; j2 < 32; j2++)
                acc += s_t[h * 33 + j2] * s_ep[j][kt + j2];
            __syncthreads();
        }
        g_hp[(p0 + j) * H_ + h] = acc;
    }

    if (bid == 0 && tid == 0) {
        #pragma unroll
        for (int p = 0; p < P_; p++) {
            const float w = expand_weight[p];
            g_pc[p] = make_float4(fabsf(w), fmaxf(-w, 0.f), gn_w[p], gn_b[p]);
        }
        for (int g = 0; g < 2; g++) {
            float A1 = 0.f, A2 = 0.f, B1 = 0.f, B2 = 0.f;
            for (int p = g * 8; p < g * 8 + 8; p++) {
                const float w  = expand_weight[p];
                const float aw = fabsf(w);
                const float v  = fmaxf(-w, 0.f);
                const float u  = aw - v;
                A1 += aw; A2 += v; B1 += u * u; B2 += v * v;
            }
            g_gc[g * 4 + 0] = A1; g_gc[g * 4 + 1] = A2;
            g_gc[g * 4 + 2] = B1; g_gc[g * 4 + 3] = B2;
        }
    }
}

// ---------------- K2: fused per-batch kernel (512 blocks, 512 threads) ----------------
// smem layout (floats):
#define SM_X     0                        // 64 x 128          (8192)
#define SM_EC    (SM_X + 64 * 128)        // 64 x 132          (8448)
#define SM_XP    (SM_EC + 64 * 132)       // 16 x 128          (2048)
#define SM_P1    (SM_XP + 16 * 128)       // 4 x [16 x 128]    (8192); q0 becomes hat
#define SM_HAT   SM_P1
#define SM_PART2 (SM_P1 + 2048)           // alias q1: [2][16][64] phase-2 partials
#define SM_MT    (SM_P1 + 4096)           // alias q2: 64 x 20 transposed m
#define SM_RED   (SM_P1 + 8192)           // 64
#define SM_GRP   (SM_RED + 64)            // 8
#define SM_FLOATS (SM_GRP + 8)            // 26952 floats = 107,808 B

extern __shared__ float sm[];

__global__ void __launch_bounds__(512, 2)
trompt_main_kernel(const float* __restrict__ x,
                   const float* __restrict__ x_prompt,
                   float* __restrict__ out)
{
    float* s_x   = sm + SM_X;
    float* s_ec  = sm + SM_EC;
    float* s_xp  = sm + SM_XP;
    float* s_p1  = sm + SM_P1;
    float* s_hat = sm + SM_HAT;
    float* s_pt2 = sm + SM_PART2;
    float* s_mt  = sm + SM_MT;
    float* s_red = sm + SM_RED;
    float* s_grp = sm + SM_GRP;

    const int tid  = threadIdx.x;
    const int b    = blockIdx.x;
    const int warp = tid >> 5;
    const int lane = tid & 31;

    // ---- loads + fused batch stats
    {
        float s1 = 0.f, sx = 0.f, sr2 = 0.f, sx2 = 0.f;
        const float4* xb4 = (const float4*)(x + (size_t)b * (C_ * H_));
        #pragma unroll
        for (int i = 0; i < 4; i++) {
            const float4 v = xb4[tid + i * 512];
            *(float4*)(s_x + (tid + i * 512) * 4) = v;
            float vv[4] = {v.x, v.y, v.z, v.w};
            #pragma unroll
            for (int q = 0; q < 4; q++) {
                const float r = fmaxf(vv[q], 0.f);
                s1 += r; sx += vv[q]; sr2 += r * r; sx2 += vv[q] * vv[q];
            }
        }
        const float4* ec4 = (const float4*)g_ec;
        #pragma unroll
        for (int i = 0; i < 4; i++) {
            const int e = tid + i * 512;
            const float4 v = ec4[e];
            const int idx = e * 4;
            *(float4*)(s_ec + (idx >> 7) * 132 + (idx & 127)) = v;
        }
        const float4* xp4 = (const float4*)(x_prompt + (size_t)b * (P_ * H_));
        *(float4*)(s_xp + tid * 4) = xp4[tid];

        #pragma unroll
        for (int o = 16; o > 0; o >>= 1) {
            s1  += __shfl_xor_sync(0xffffffffu, s1,  o);
            sx  += __shfl_xor_sync(0xffffffffu, sx,  o);
            sr2 += __shfl_xor_sync(0xffffffffu, sr2, o);
            sx2 += __shfl_xor_sync(0xffffffffu, sx2, o);
        }
        if (lane == 0) {
            s_red[warp * 4 + 0] = s1;  s_red[warp * 4 + 1] = sx;
            s_red[warp * 4 + 2] = sr2; s_red[warp * 4 + 3] = sx2;
        }
    }
    __syncthreads();

    const int h = tid & 127;

    // ---- phase 1: partial hat; thread = (h, q k-quarter), 16 p per thread
    {
        const int q  = tid >> 7;    // 0..3 -> kq in [q*8, q*8+8)
        u64 acc[16];
        #pragma unroll
        for (int p = 0; p < 16; p++) acc[p] = 0;
        const ulonglong2* w2 = (const ulonglong2*)g_W2q;
        #pragma unroll
        for (int kq = 0; kq < 8; kq++) {
            const int kk = q * 8 + kq;
            const ulonglong2 w = w2[kk * H_ + h];
            #pragma unroll
            for (int p = 0; p < 16; p++) {
                const ulonglong2 xpv = *(const ulonglong2*)(s_xp + p * H_ + kk * 4);
                acc[p] = fma2(xpv.x, w.x, acc[p]);
                acc[p] = fma2(xpv.y, w.y, acc[p]);
            }
        }
        float* dst = s_p1 + q * 2048;
        #pragma unroll
        for (int p = 0; p < 16; p++) {
            const float2 r = unpack2(acc[p]);
            dst[p * H_ + h] = r.x + r.y;
        }
    }
    __syncthreads();

    // ---- phase 1 reduce: hat = sum(quarters) + hp + xp  (in-place into q0)
    {
        const float4 r0 = *(const float4*)(s_p1 + tid * 4);
        const float4 r1 = *(const float4*)(s_p1 + 2048 + tid * 4);
        const float4 r2 = *(const float4*)(s_p1 + 4096 + tid * 4);
        const float4 r3 = *(const float4*)(s_p1 + 6144 + tid * 4);
        const float4 hp = ((const float4*)g_hp)[tid];
        const float4 xp = *(const float4*)(s_xp + tid * 4);
        float4 o;
        o.x = r0.x + r1.x + r2.x + r3.x + hp.x + xp.x;
        o.y = r0.y + r1.y + r2.y + r3.y + hp.y + xp.y;
        o.z = r0.z + r1.z + r2.z + r3.z + hp.z + xp.z;
        o.w = r0.w + r1.w + r2.w + r3.w + hp.w + xp.w;
        *(float4*)(s_hat + tid * 4) = o;
    }
    __syncthreads();

    // ---- phase 2: m partials; thread = (c, pg of 4p, hs h-half)
    {
        const int c  = tid & 63;
        const int pg = (tid >> 6) & 3;
        const int hs = tid >> 8;
        const int p0 = pg * 4;
        const int hb = hs * 64;
        u64 aa[4] = {0,0,0,0}, ab[4] = {0,0,0,0};
        #pragma unroll
        for (int hh = 0; hh < 64; hh += 4) {
            const ulonglong2 e = *(const ulonglong2*)(s_ec + c * 132 + hb + hh);
            #pragma unroll
            for (int j = 0; j < 4; j++) {
                const ulonglong2 t = *(const ulonglong2*)(s_hat + (p0 + j) * H_ + hb + hh);
                aa[j] = fma2(e.x, t.x, aa[j]);
                ab[j] = fma2(e.y, t.y, ab[j]);
            }
        }
        #pragma unroll
        for (int j = 0; j < 4; j++) {
            const float2 ra = unpack2(aa[j]);
            const float2 rb = unpack2(ab[j]);
            s_pt2[hs * 1024 + (p0 + j) * 64 + c] = (ra.x + ra.y) + (rb.x + rb.y);
        }
    }
    __syncthreads();

    // ---- softmax (warp = p): sum h-halves, softmax over c, store transposed s_mt[c][p]
    {
        const int p = warp;
        const float v0 = s_pt2[p * 64 + lane]        + s_pt2[1024 + p * 64 + lane];
        const float v1 = s_pt2[p * 64 + 32 + lane]   + s_pt2[1024 + p * 64 + 32 + lane];
        float mx = fmaxf(v0, v1);
        #pragma unroll
        for (int o = 16; o > 0; o >>= 1)
            mx = fmaxf(mx, __shfl_xor_sync(0xffffffffu, mx, o));
        const float e0 = __expf(v0 - mx);
        const float e1 = __expf(v1 - mx);
        float s = e0 + e1;
        #pragma unroll
        for (int o = 16; o > 0; o >>= 1)
            s += __shfl_xor_sync(0xffffffffu, s, o);
        const float inv = 1.f / s;
        s_mt[lane * 20 + p]        = e0 * inv;
        s_mt[(lane + 32) * 20 + p] = e1 * inv;

        if (tid == 0) {
            float S1 = 0.f, Sx = 0.f, Sr2 = 0.f, Sx2 = 0.f;
            #pragma unroll
            for (int w = 0; w < 16; w++) {
                S1 += s_red[w * 4 + 0]; Sx  += s_red[w * 4 + 1];
                Sr2 += s_red[w * 4 + 2]; Sx2 += s_red[w * 4 + 3];
            }
            const float invN = 1.f / 65536.f;
            #pragma unroll
            for (int g = 0; g < 2; g++) {
                const float A1 = g_gc[g * 4 + 0], A2 = g_gc[g * 4 + 1];
                const float B1 = g_gc[g * 4 + 2], B2 = g_gc[g * 4 + 3];
                const float mu = (A1 * S1 - A2 * Sx) * invN;
                const float E2 = (B1 * Sr2 + B2 * (Sx2 - Sr2)) * invN;
                s_grp[g * 2 + 0] = mu;
                s_grp[g * 2 + 1] = rsqrtf(E2 - mu * mu + EPS_);
            }
        }
    }
    __syncthreads();

    // ---- phase 4: out[p,h]; thread = (h, pb); packed over p-pairs
    {
        const int pb = tid >> 7;
        float c1[4], c2[4], c3[4];
        #pragma unroll
        for (int j = 0; j < 4; j++) {
            const int p = pb * 4 + j;
            const float4 pc = g_pc[p];
            const int g = p >> 3;
            const float mu = s_grp[g * 2 + 0];
            const float rs = s_grp[g * 2 + 1];
            const float gr = pc.z * rs;
            c1[j] = gr * pc.x;
            c2[j] = 1.f - gr * pc.y;
            c3[j] = pc.w - gr * mu;
        }
        u64 accR01 = 0, accR23 = 0, accX01 = 0, accX23 = 0;
        for (int c = 0; c < C_; c++) {
            const float xv = s_x[c * H_ + h];
            const float rv = fmaxf(xv, 0.f);
            const u64 rr = pack2(rv, rv);
            const u64 xx = pack2(xv, xv);
            const ulonglong2 mq = *(const ulonglong2*)(s_mt + c * 20 + pb * 4);
            accR01 = fma2(mq.x, rr, accR01);
            accR23 = fma2(mq.y, rr, accR23);
            accX01 = fma2(mq.x, xx, accX01);
            accX23 = fma2(mq.y, xx, accX23);
        }
        const float2 R01 = unpack2(accR01), R23 = unpack2(accR23);
        const float2 X01 = unpack2(accX01), X23 = unpack2(accX23);
        float* ob = out + (size_t)b * (P_ * H_);
        ob[(pb * 4 + 0) * H_ + h] = c1[0] * R01.x + c2[0] * X01.x + c3[0];
        ob[(pb * 4 + 1) * H_ + h] = c1[1] * R01.y + c2[1] * X01.y + c3[1];
        ob[(pb * 4 + 2) * H_ + h] = c1[2] * R23.x + c2[2] * X23.x + c3[2];
        ob[(pb * 4 + 3) * H_ + h] = c1[3] * R23.y + c2[3] * X23.y + c3[3];
    }
}

// ---------------- launch ----------------
extern "C" void kernel_launch(void* const* d_in, const int* in_sizes, int n_in,
                              void* d_out, int out_size)
{
    const float* x          = (const float*)d_in[0];
    const float* x_prompt   = (const float*)d_in[1];
    const float* emb_column = (const float*)d_in[2];
    const float* emb_prompt = (const float*)d_in[3];
    const float* lin_w      = (const float*)d_in[4];
    const float* lin_b      = (const float*)d_in[5];
    const float* ln_col_w   = (const float*)d_in[6];
    const float* ln_col_b   = (const float*)d_in[7];
    const float* ln_pr_w    = (const float*)d_in[8];
    const float* ln_pr_b    = (const float*)d_in[9];
    const float* expand_w   = (const float*)d_in[10];
    const float* gn_w       = (const float*)d_in[11];
    const float* gn_b       = (const float*)d_in[12];
    float* out = (float*)d_out;

    const int smemBytes = SM_FLOATS * (int)sizeof(float);   // 107,808 B
    cudaFuncSetAttribute(trompt_main_kernel,
                         cudaFuncAttributeMaxDynamicSharedMemorySize, smemBytes);

    setup_kernel<<<9, 512>>>(emb_column, emb_prompt, lin_w, lin_b,
                             ln_col_w, ln_col_b, ln_pr_w, ln_pr_b,
                             expand_w, gn_w, gn_b);
    trompt_main_kernel<<<B_, 512, smemBytes>>>(x, x_prompt, out);
}